// round 4
// baseline (speedup 1.0000x reference)
#include <cuda_runtime.h>
#include <math.h>

// Problem constants: T=70, B=64, V=10000, E=512, H=1024, L=2
#define T_  70
#define B_  64
#define V_  10000
#define E_  512
#define H_  1024
#define MTOT (T_ * B_)          // 4480 = 35 * 128
#define BH   (B_ * H_)          // 65536

// Scratch (__device__ globals: allocation-free rule)
__device__ float g_X0[(size_t)MTOT * H_];
__device__ float g_H0[(size_t)MTOT * H_];
__device__ float g_X1[(size_t)MTOT * H_];
__device__ float g_H1[(size_t)MTOT * H_];
__device__ float g_P[(size_t)16 * BH];      // k-split partials [16][64][1024]
__device__ unsigned g_flags[128];            // per-block barrier flags

__global__ void bar_init() { g_flags[threadIdx.x] = 0u; }

// ---------------------------------------------------------------------------
// Contention-free grid barrier (128 co-resident blocks).
// Arrival: one plain-ish store per block to its OWN flag (no RMW pileup).
// Wait: 128 threads each poll one distinct flag -> L2 serves broadcast reads.
// Phases are monotonically increasing within a launch; flags zeroed by
// bar_init before each persistent launch (graph-replay safe).
// ---------------------------------------------------------------------------
__device__ __forceinline__ void gridbar(int bid, unsigned phase) {
    __threadfence();
    __syncthreads();
    if (threadIdx.x == 0)
        atomicExch(&g_flags[bid], phase);
    if (threadIdx.x < 128) {
        volatile unsigned* vf = g_flags;
        while (vf[threadIdx.x] < phase) { }
    }
    __syncthreads();
    __threadfence();
}

// P-column permutation: compute threads store their 8 n's (n = j*8 + tn)
// at contiguous p-index tn*8 + j.
__device__ __forceinline__ int pidx(int n) {
    const int nl = n & 63;
    return (n & ~63) | ((nl & 7) << 3) | (nl >> 3);
}

// ---------------------------------------------------------------------------
// Persistent recurrence: one launch runs all T=70 steps of one layer.
// Grid 128 blocks x 256 threads. Block (ntile = bid>>3, ks = bid&7) owns
// W rows [ntile*64,+64) x cols [ks*128,+128) resident in SMEM for the whole
// kernel. Per step: partial C[64m x 64n] over 128 k -> 16 gmem partial sets
// (incl. in-block k-half split) -> barrier -> reduce+X+tanh -> barrier.
// ---------------------------------------------------------------------------
__global__ __launch_bounds__(256) void rnn_layer(
    const float* __restrict__ X, const float* __restrict__ hinit,
    const float* __restrict__ W, float* __restrict__ Hall)
{
    __shared__ float Ws[64][132];

    const int tid   = threadIdx.x;
    const int bid   = blockIdx.x;
    const int ntile = bid >> 3;           // 0..15
    const int ks    = bid & 7;            // 0..7
    const int n0    = ntile * 64;
    const int kb    = ks * 128;

    // Load W slice once (resident across all steps)
    {
        const int r  = tid >> 2;          // 0..63
        const int q4 = (tid & 3) * 4;     // 0,4,8,12
        #pragma unroll
        for (int s = 0; s < 8; s++) {
            const int c = q4 + s * 16;
            *(float4*)&Ws[r][c] = *(const float4*)&W[(size_t)(n0 + r) * H_ + kb + c];
        }
    }
    __syncthreads();

    const int kh   = tid >> 7;            // k-half 0/1 (64 k each)
    const int t7   = tid & 127;
    const int tm   = t7 & 15;             // m-group (4 rows)
    const int tn   = t7 >> 4;             // 0..7
    const int m0   = tm * 4;
    const int kloc = kh * 64;
    float* Pp = g_P + (size_t)(ks * 2 + kh) * BH;

    const int e  = bid * 512 + tid * 2;   // reduce mapping
    const int rm = e >> 10;
    const int rn = e & 1023;
    const int pi0 = pidx(rn), pi1 = pidx(rn + 1);

    unsigned phase = 0;

    for (int t = 0; t < T_; t++) {
        const float* hp = t ? (Hall + (size_t)(t - 1) * BH) : hinit;

        float acc[4][8];
        #pragma unroll
        for (int i = 0; i < 4; i++)
            #pragma unroll
            for (int j = 0; j < 8; j++) acc[i][j] = 0.f;

        #pragma unroll 4
        for (int kq = 0; kq < 16; kq++) {
            const int kl = kloc + kq * 4;
            const int k  = kb + kl;
            float4 hv[4];
            #pragma unroll
            for (int i = 0; i < 4; i++)
                hv[i] = *(const float4*)&hp[(size_t)(m0 + i) * H_ + k];
            #pragma unroll
            for (int j = 0; j < 8; j++) {
                const float4 wv = *(const float4*)&Ws[j * 8 + tn][kl];
                #pragma unroll
                for (int i = 0; i < 4; i++)
                    acc[i][j] += hv[i].x * wv.x + hv[i].y * wv.y
                               + hv[i].z * wv.z + hv[i].w * wv.w;
            }
        }

        // Store partial (permuted n layout -> contiguous float4s)
        #pragma unroll
        for (int i = 0; i < 4; i++) {
            float* dst = Pp + (size_t)(m0 + i) * H_ + n0 + tn * 8;
            *(float4*)dst       = make_float4(acc[i][0], acc[i][1], acc[i][2], acc[i][3]);
            *(float4*)(dst + 4) = make_float4(acc[i][4], acc[i][5], acc[i][6], acc[i][7]);
        }

        gridbar(bid, ++phase);

        // Reduce 16 partials + X, tanh, write h_t (L2 reads of P)
        {
            const float* Xt = X + (size_t)t * BH;
            float s0 = Xt[e], s1 = Xt[e + 1];
            const size_t base = (size_t)rm * H_;
            #pragma unroll
            for (int j = 0; j < 16; j++) {
                const float* pj = g_P + (size_t)j * BH + base;
                s0 += __ldcg(pj + pi0);
                s1 += __ldcg(pj + pi1);
            }
            float* Ht = Hall + (size_t)t * BH;
            Ht[e]     = tanhf(s0);
            Ht[e + 1] = tanhf(s1);
        }

        gridbar(bid, ++phase);
    }
}

// ---------------------------------------------------------------------------
// TF32 tensor-core GEMM: C[m,n] = A[m,:] . B[n,:] + bias[n]
// A: [M,K] row-major (optional gather), B: [N,K] row-major, fp32 accum.
// Block 128x128, kc=16 double-buffered, 8 warps (4m x 2n), warp 32m x 64n.
// Smem k-slot permutation within each 8-k group: slot = (k&3)*2 + ((k>>2)&1),
// so a lane's (k=tig, k=tig+4) fragment pair is one aligned LDS.64.
// Row stride 20 -> 2 wavefronts per LDS.64 (the 256B floor), no conflicts.
// ---------------------------------------------------------------------------
__device__ __forceinline__ unsigned f2tf(float x) {
    unsigned r; asm("cvt.rna.tf32.f32 %0, %1;" : "=r"(r) : "f"(x)); return r;
}
__device__ __forceinline__ void mma_tf32(float c[4], const unsigned a[4], const unsigned b[2]) {
    asm volatile(
        "mma.sync.aligned.m16n8k8.row.col.f32.tf32.tf32.f32 "
        "{%0,%1,%2,%3}, {%4,%5,%6,%7}, {%8,%9}, {%0,%1,%2,%3};\n"
        : "+f"(c[0]), "+f"(c[1]), "+f"(c[2]), "+f"(c[3])
        : "r"(a[0]), "r"(a[1]), "r"(a[2]), "r"(a[3]), "r"(b[0]), "r"(b[1]));
}

__global__ __launch_bounds__(256, 2) void gemm_tf32(
    const float* __restrict__ A, const float* __restrict__ Bm,
    const float* __restrict__ bias, float* __restrict__ C,
    const int* __restrict__ gidx, int N, int K, int ldc)
{
    __shared__ unsigned As[2][128][20];
    __shared__ unsigned Bs[2][128][20];

    const int tid  = threadIdx.x;
    const int lane = tid & 31, warp = tid >> 5;
    const int wm = warp >> 1, wn = warp & 1;
    const int gid = lane >> 2, tig = lane & 3;
    const int bm = blockIdx.y * 128, bn = blockIdx.x * 128;

    // Loader: thread covers rows lr and lr+64, k-quad lq within the stage
    const int lr = tid >> 2;
    const int lq = (tid & 3) * 4;
    const int sb = ((lq & 4) ? 1 : 0) + (lq & 8);   // permuted slot base
    const float* Ar0 = A + (size_t)(gidx ? gidx[bm + lr]      : (bm + lr))      * K;
    const float* Ar1 = A + (size_t)(gidx ? gidx[bm + lr + 64] : (bm + lr + 64)) * K;
    const int nr0 = bn + lr, nr1 = bn + lr + 64;
    const bool bok0 = nr0 < N, bok1 = nr1 < N;
    const float* Br0 = Bm + (size_t)nr0 * K;
    const float* Br1 = Bm + (size_t)nr1 * K;
    const float4 z4 = make_float4(0.f, 0.f, 0.f, 0.f);

    const int nst = K >> 4;

    // Permuted scatter of a converted float4 into a stage row
    #define STORE4(arr, buf_, row_, v)                                  \
        { unsigned* rp = &arr[buf_][row_][0];                           \
          rp[sb + 0] = f2tf((v).x); rp[sb + 2] = f2tf((v).y);           \
          rp[sb + 4] = f2tf((v).z); rp[sb + 6] = f2tf((v).w); }

    // Stage 0
    {
        float4 a0 = *(const float4*)(Ar0 + lq);
        float4 a1 = *(const float4*)(Ar1 + lq);
        float4 b0 = bok0 ? *(const float4*)(Br0 + lq) : z4;
        float4 b1 = bok1 ? *(const float4*)(Br1 + lq) : z4;
        STORE4(As, 0, lr, a0); STORE4(As, 0, lr + 64, a1);
        STORE4(Bs, 0, lr, b0); STORE4(Bs, 0, lr + 64, b1);
    }
    __syncthreads();

    float acc[2][8][4];
    #pragma unroll
    for (int i = 0; i < 2; i++)
        #pragma unroll
        for (int j = 0; j < 8; j++)
            #pragma unroll
            for (int q = 0; q < 4; q++) acc[i][j][q] = 0.f;

    for (int s = 0; s < nst; s++) {
        const int buf = s & 1;
        float4 na0, na1, nb0, nb1;
        const bool more = (s + 1 < nst);
        if (more) {
            const int ko = (s + 1) * 16 + lq;
            na0 = *(const float4*)(Ar0 + ko);
            na1 = *(const float4*)(Ar1 + ko);
            nb0 = bok0 ? *(const float4*)(Br0 + ko) : z4;
            nb1 = bok1 ? *(const float4*)(Br1 + ko) : z4;
        }

        #pragma unroll
        for (int kk = 0; kk < 16; kk += 8) {
            unsigned af[2][4];
            #pragma unroll
            for (int i = 0; i < 2; i++) {
                const int r = wm * 32 + i * 16 + gid;
                const uint2 p0 = *(const uint2*)&As[buf][r    ][kk + tig * 2];
                const uint2 p1 = *(const uint2*)&As[buf][r + 8][kk + tig * 2];
                af[i][0] = p0.x; af[i][1] = p1.x; af[i][2] = p0.y; af[i][3] = p1.y;
            }
            #pragma unroll
            for (int j = 0; j < 8; j++) {
                const int r = wn * 64 + j * 8 + gid;
                const uint2 pb = *(const uint2*)&Bs[buf][r][kk + tig * 2];
                unsigned bf[2] = { pb.x, pb.y };
                mma_tf32(acc[0][j], af[0], bf);
                mma_tf32(acc[1][j], af[1], bf);
            }
        }

        if (more) {
            const int nb = buf ^ 1;
            STORE4(As, nb, lr, na0); STORE4(As, nb, lr + 64, na1);
            STORE4(Bs, nb, lr, nb0); STORE4(Bs, nb, lr + 64, nb1);
        }
        __syncthreads();
    }
    #undef STORE4

    // Epilogue: c0/c1 -> (row, col..col+1), c2/c3 -> (row+8, ...)
    #pragma unroll
    for (int i = 0; i < 2; i++) {
        const int rg = bm + wm * 32 + i * 16 + gid;
        #pragma unroll
        for (int j = 0; j < 8; j++) {
            const int cg = bn + wn * 64 + j * 8 + tig * 2;
            if (cg < N) {
                const float2 bb = *(const float2*)&bias[cg];
                float2 c01 = make_float2(acc[i][j][0] + bb.x, acc[i][j][1] + bb.y);
                float2 c23 = make_float2(acc[i][j][2] + bb.x, acc[i][j][3] + bb.y);
                *(float2*)&C[(size_t)rg * ldc + cg]       = c01;
                *(float2*)&C[(size_t)(rg + 8) * ldc + cg] = c23;
            }
        }
    }
}

// h_final = [H0[T-1], H1[T-1]] -> d_out tail
__global__ void copy_final(const float* __restrict__ H0,
                           const float* __restrict__ H1,
                           float* __restrict__ dst)
{
    const int i = blockIdx.x * blockDim.x + threadIdx.x;
    if (i < BH)          dst[i] = H0[(size_t)(T_ - 1) * BH + i];
    else if (i < 2 * BH) dst[i] = H1[(size_t)(T_ - 1) * BH + (i - BH)];
}

extern "C" void kernel_launch(void* const* d_in, const int* in_sizes, int n_in,
                              void* d_out, int out_size)
{
    (void)in_sizes; (void)n_in; (void)out_size;
    const int*   inputs = (const int*)  d_in[0];
    const float* hidden = (const float*)d_in[1];
    const float* emb    = (const float*)d_in[2];
    const float* Wx0    = (const float*)d_in[3];
    const float* Wx1    = (const float*)d_in[4];
    const float* Wh0    = (const float*)d_in[5];
    const float* bh0    = (const float*)d_in[6];
    const float* Wh1    = (const float*)d_in[7];
    const float* bh1    = (const float*)d_in[8];
    const float* Wy     = (const float*)d_in[9];
    const float* by     = (const float*)d_in[10];
    float* out = (float*)d_out;                    // [T*B*V][L*B*H]

    float *X0, *H0, *X1, *H1;
    cudaGetSymbolAddress((void**)&X0, g_X0);
    cudaGetSymbolAddress((void**)&H0, g_H0);
    cudaGetSymbolAddress((void**)&X1, g_X1);
    cudaGetSymbolAddress((void**)&H1, g_H1);

    // A: X0 = gather(emb) @ Wx0^T + bh0
    gemm_tf32<<<dim3(H_ / 128, MTOT / 128), 256>>>(emb, Wx0, bh0, X0, inputs, H_, E_, H_);

    // B: layer-0 recurrence (persistent, 70 steps, flag barriers)
    bar_init<<<1, 128>>>();
    rnn_layer<<<128, 256>>>(X0, hidden, Wh0, H0);

    // C: X1 = H0 @ Wx1^T + bh1
    gemm_tf32<<<dim3(H_ / 128, MTOT / 128), 256>>>(H0, Wx1, bh1, X1, nullptr, H_, H_, H_);

    // D: layer-1 recurrence
    bar_init<<<1, 128>>>();
    rnn_layer<<<128, 256>>>(X1, hidden + BH, Wh1, H1);

    // E: logits = H1 @ Wy^T + by
    gemm_tf32<<<dim3((V_ + 127) / 128, MTOT / 128), 256>>>(H1, Wy, by, out, nullptr, V_, H_, V_);

    // F: h_final tail
    copy_final<<<(2 * BH + 255) / 256, 256>>>(H0, H1, out + (size_t)MTOT * V_);
}

// round 5
// speedup vs baseline: 1.5525x; 1.5525x over previous
#include <cuda_runtime.h>
#include <math.h>

// Problem constants: T=70, B=64, V=10000, E=512, H=1024, L=2
#define T_  70
#define B_  64
#define V_  10000
#define E_  512
#define H_  1024
#define MTOT (T_ * B_)          // 4480 = 35 * 128
#define BH   (B_ * H_)          // 65536

// Scratch (__device__ globals: allocation-free rule)
__device__ float    g_X0[(size_t)MTOT * H_];
__device__ float    g_H0[(size_t)MTOT * H_];
__device__ float    g_X1[(size_t)MTOT * H_];
__device__ float    g_H1[(size_t)MTOT * H_];
__device__ float    g_P[(size_t)16 * BH];       // k-split partials [16][64][1024]
__device__ unsigned g_Htf[(size_t)T_ * BH];     // tf32 copy of h_t (k-pair interleaved)
__device__ unsigned g_flags[128];               // per-block barrier flags

__global__ void bar_init() { g_flags[threadIdx.x] = 0u; }

// Contention-free grid barrier (128 co-resident blocks, 1/SM).
__device__ __forceinline__ void gridbar(int bid, unsigned phase) {
    __threadfence();
    __syncthreads();
    if (threadIdx.x == 0)
        atomicExch(&g_flags[bid], phase);
    if (threadIdx.x < 128) {
        volatile unsigned* vf = g_flags;
        while (vf[threadIdx.x] < phase) { }
    }
    __syncthreads();
    __threadfence();
}

__device__ __forceinline__ unsigned f2tf(float x) {
    unsigned r; asm("cvt.rna.tf32.f32 %0, %1;" : "=r"(r) : "f"(x)); return r;
}
__device__ __forceinline__ void mma_tf32(float c[4], const unsigned a[4], const unsigned b[2]) {
    asm volatile(
        "mma.sync.aligned.m16n8k8.row.col.f32.tf32.tf32.f32 "
        "{%0,%1,%2,%3}, {%4,%5,%6,%7}, {%8,%9}, {%0,%1,%2,%3};\n"
        : "+f"(c[0]), "+f"(c[1]), "+f"(c[2]), "+f"(c[3])
        : "r"(a[0]), "r"(a[1]), "r"(a[2]), "r"(a[3]), "r"(b[0]), "r"(b[1]));
}

// ---------------------------------------------------------------------------
// Persistent recurrence with tensor cores. 128 blocks x 256 threads.
// Block (ntile=bid>>3, ks=bid&7) owns W rows [ntile*64,+64) x k [ks*128,+128),
// held in SMEM as tf32 hi/lo split (W-side rounding ~exactly compensated).
// Warps: wk = wid&1 (k-half of 64), wn = wid>>1 (16-n strip). Warp computes
// C[64m x 16n] over its 64 k via m16n8k8 tf32 MMAs (hi+lo chains).
// A (=h_{t-1}) read from g_Htf[t-1] (tf32, k-pair interleaved: within each
// 8-k group, k=off stored at (off&3)*2+(off>>2), so (k,k+4) = one LDG.64).
// Partials -> g_P[ks*2+wk] -> barrier -> reduce(+X)+tanh -> Hall fp32 +
// g_Htf[t] -> barrier.
// ---------------------------------------------------------------------------
__global__ __launch_bounds__(256) void rnn_layer(
    const float* __restrict__ X, const float* __restrict__ hinit,
    const float* __restrict__ W, float* __restrict__ Hall)
{
    extern __shared__ unsigned sw[];
    unsigned* Whi = sw;                 // [64][132]
    unsigned* Wlo = sw + 64 * 132;      // [64][132]

    const int tid = threadIdx.x;
    const int bid = blockIdx.x;
    const int ntile = bid >> 3;         // 0..15
    const int ks    = bid & 7;          // 0..7
    const int n0    = ntile * 64;
    const int kb    = ks * 128;

    // Load + split W slice once (resident all steps)
    {
        const int r  = tid >> 2;        // 0..63
        const int q4 = (tid & 3) * 4;
        #pragma unroll
        for (int s = 0; s < 8; s++) {
            const int c = q4 + s * 16;
            const float4 w = *(const float4*)&W[(size_t)(n0 + r) * H_ + kb + c];
            unsigned h0 = f2tf(w.x), h1 = f2tf(w.y), h2 = f2tf(w.z), h3 = f2tf(w.w);
            unsigned* ph = &Whi[r * 132 + c];
            unsigned* pl = &Wlo[r * 132 + c];
            ph[0] = h0; ph[1] = h1; ph[2] = h2; ph[3] = h3;
            pl[0] = f2tf(w.x - __uint_as_float(h0));
            pl[1] = f2tf(w.y - __uint_as_float(h1));
            pl[2] = f2tf(w.z - __uint_as_float(h2));
            pl[3] = f2tf(w.w - __uint_as_float(h3));
        }
    }
    __syncthreads();

    const int wid  = tid >> 5, lane = tid & 31;
    const int wk   = wid & 1;           // k-half (64 k)
    const int wn   = wid >> 1;          // 0..3 (16-n strip)
    const int gid  = lane >> 2, tig = lane & 3;
    const int kwb  = kb + wk * 64;      // global k base for this warp
    const int klb  = wk * 64;           // smem-local k base

    float* Pp = g_P + (size_t)(ks * 2 + wk) * BH;

    // Reduce mapping: thread covers elements e, e+1 of [64][1024]
    const int e  = bid * 512 + tid * 2;
    const int rm = e >> 10;
    const int rn = e & 1023;
    const int b8 = rn & ~7;
    const int o0 = rn & 7;              // even
    const int tp0 = b8 + ((o0 & 3) * 2) + (o0 >> 2);
    const int tp1 = b8 + (((o0 + 1) & 3) * 2) + ((o0 + 1) >> 2);

    unsigned phase = 0;

    for (int t = 0; t < T_; t++) {
        float acc[4][2][4];
        #pragma unroll
        for (int im = 0; im < 4; im++)
            #pragma unroll
            for (int j = 0; j < 2; j++)
                #pragma unroll
                for (int q = 0; q < 4; q++) acc[im][j][q] = 0.f;

        const unsigned* Hp = g_Htf + (size_t)(t - 1) * BH;   // valid for t>0

        #pragma unroll 2
        for (int kk = 0; kk < 8; kk++) {
            const int kcol = kwb + kk * 8;
            unsigned af[4][4];
            if (t == 0) {
                #pragma unroll
                for (int im = 0; im < 4; im++) {
                    const int r0 = im * 16 + gid;
                    af[im][0] = f2tf(hinit[(size_t)r0 * H_ + kcol + tig]);
                    af[im][1] = f2tf(hinit[(size_t)(r0 + 8) * H_ + kcol + tig]);
                    af[im][2] = f2tf(hinit[(size_t)r0 * H_ + kcol + tig + 4]);
                    af[im][3] = f2tf(hinit[(size_t)(r0 + 8) * H_ + kcol + tig + 4]);
                }
            } else {
                #pragma unroll
                for (int im = 0; im < 4; im++) {
                    const int r0 = im * 16 + gid;
                    const uint2 p0 = *(const uint2*)&Hp[(size_t)r0 * H_ + kcol + tig * 2];
                    const uint2 p1 = *(const uint2*)&Hp[(size_t)(r0 + 8) * H_ + kcol + tig * 2];
                    af[im][0] = p0.x; af[im][1] = p1.x;
                    af[im][2] = p0.y; af[im][3] = p1.y;
                }
            }
            #pragma unroll
            for (int j = 0; j < 2; j++) {
                const int wrow = (wn * 16 + j * 8 + gid) * 132 + klb + kk * 8;
                unsigned bh[2] = { Whi[wrow + tig], Whi[wrow + tig + 4] };
                unsigned bl[2] = { Wlo[wrow + tig], Wlo[wrow + tig + 4] };
                #pragma unroll
                for (int im = 0; im < 4; im++) {
                    mma_tf32(acc[im][j], af[im], bh);
                    mma_tf32(acc[im][j], af[im], bl);
                }
            }
        }

        // Store partials: warp covers all 64 m x its 16 n
        #pragma unroll
        for (int im = 0; im < 4; im++) {
            const int r0 = im * 16 + gid;
            #pragma unroll
            for (int j = 0; j < 2; j++) {
                const int col = n0 + wn * 16 + j * 8 + tig * 2;
                *(float2*)&Pp[(size_t)r0 * H_ + col] =
                    make_float2(acc[im][j][0], acc[im][j][1]);
                *(float2*)&Pp[(size_t)(r0 + 8) * H_ + col] =
                    make_float2(acc[im][j][2], acc[im][j][3]);
            }
        }

        gridbar(bid, ++phase);

        // Reduce 16 partials + X, tanh -> Hall fp32 + Htf tf32(interleaved)
        {
            const float2 xv = *(const float2*)&X[(size_t)t * BH + e];
            float s0 = xv.x, s1 = xv.y;
            const size_t base = (size_t)rm * H_ + rn;
            #pragma unroll
            for (int j = 0; j < 16; j++) {
                const float2 v = __ldcg((const float2*)&g_P[(size_t)j * BH + base]);
                s0 += v.x; s1 += v.y;
            }
            const float h0 = tanhf(s0), h1 = tanhf(s1);
            *(float2*)&Hall[(size_t)t * BH + e] = make_float2(h0, h1);
            unsigned* Ht = g_Htf + (size_t)t * BH + (size_t)rm * H_;
            Ht[tp0] = f2tf(h0);
            Ht[tp1] = f2tf(h1);
        }

        gridbar(bid, ++phase);
    }
}

// ---------------------------------------------------------------------------
// TF32 tensor-core GEMM (round-3 version, measured 88us @ grid 280).
// C[m,n] = A[m,:] . B[n,:] + bias[n]; block 128x128, kc=16 double-buffered,
// 8 warps (4m x 2n), warp 32m x 64n. Scalar LDS at stride 20: conflict-free.
// ---------------------------------------------------------------------------
__global__ __launch_bounds__(256, 2) void gemm_tf32(
    const float* __restrict__ A, const float* __restrict__ Bm,
    const float* __restrict__ bias, float* __restrict__ C,
    const int* __restrict__ gidx, int N, int K, int ldc)
{
    __shared__ unsigned As[2][128][20];
    __shared__ unsigned Bs[2][128][20];

    const int tid  = threadIdx.x;
    const int lane = tid & 31, warp = tid >> 5;
    const int wm = warp >> 1, wn = warp & 1;
    const int gid = lane >> 2, tig = lane & 3;
    const int bm = blockIdx.y * 128, bn = blockIdx.x * 128;

    const int lr = tid >> 2;
    const int lq = (tid & 3) * 4;
    const float* Ar0 = A + (size_t)(gidx ? gidx[bm + lr]      : (bm + lr))      * K;
    const float* Ar1 = A + (size_t)(gidx ? gidx[bm + lr + 64] : (bm + lr + 64)) * K;
    const int nr0 = bn + lr, nr1 = bn + lr + 64;
    const bool bok0 = nr0 < N, bok1 = nr1 < N;
    const float* Br0 = Bm + (size_t)nr0 * K;
    const float* Br1 = Bm + (size_t)nr1 * K;
    const float4 z4 = make_float4(0.f, 0.f, 0.f, 0.f);

    const int nst = K >> 4;

    {
        float4 a0 = *(const float4*)(Ar0 + lq);
        float4 a1 = *(const float4*)(Ar1 + lq);
        float4 b0 = bok0 ? *(const float4*)(Br0 + lq) : z4;
        float4 b1 = bok1 ? *(const float4*)(Br1 + lq) : z4;
        *(uint4*)&As[0][lr     ][lq] = make_uint4(f2tf(a0.x), f2tf(a0.y), f2tf(a0.z), f2tf(a0.w));
        *(uint4*)&As[0][lr + 64][lq] = make_uint4(f2tf(a1.x), f2tf(a1.y), f2tf(a1.z), f2tf(a1.w));
        *(uint4*)&Bs[0][lr     ][lq] = make_uint4(f2tf(b0.x), f2tf(b0.y), f2tf(b0.z), f2tf(b0.w));
        *(uint4*)&Bs[0][lr + 64][lq] = make_uint4(f2tf(b1.x), f2tf(b1.y), f2tf(b1.z), f2tf(b1.w));
    }
    __syncthreads();

    float acc[2][8][4];
    #pragma unroll
    for (int i = 0; i < 2; i++)
        #pragma unroll
        for (int j = 0; j < 8; j++)
            #pragma unroll
            for (int q = 0; q < 4; q++) acc[i][j][q] = 0.f;

    for (int s = 0; s < nst; s++) {
        const int buf = s & 1;
        float4 na0, na1, nb0, nb1;
        const bool more = (s + 1 < nst);
        if (more) {
            const int ko = (s + 1) * 16 + lq;
            na0 = *(const float4*)(Ar0 + ko);
            na1 = *(const float4*)(Ar1 + ko);
            nb0 = bok0 ? *(const float4*)(Br0 + ko) : z4;
            nb1 = bok1 ? *(const float4*)(Br1 + ko) : z4;
        }

        #pragma unroll
        for (int kk = 0; kk < 16; kk += 8) {
            unsigned af[2][4];
            #pragma unroll
            for (int i = 0; i < 2; i++) {
                const int r = wm * 32 + i * 16 + gid;
                af[i][0] = As[buf][r    ][kk + tig];
                af[i][1] = As[buf][r + 8][kk + tig];
                af[i][2] = As[buf][r    ][kk + tig + 4];
                af[i][3] = As[buf][r + 8][kk + tig + 4];
            }
            #pragma unroll
            for (int j = 0; j < 8; j++) {
                const int r = wn * 64 + j * 8 + gid;
                unsigned bf[2] = { Bs[buf][r][kk + tig], Bs[buf][r][kk + tig + 4] };
                mma_tf32(acc[0][j], af[0], bf);
                mma_tf32(acc[1][j], af[1], bf);
            }
        }

        if (more) {
            const int nb = buf ^ 1;
            *(uint4*)&As[nb][lr     ][lq] = make_uint4(f2tf(na0.x), f2tf(na0.y), f2tf(na0.z), f2tf(na0.w));
            *(uint4*)&As[nb][lr + 64][lq] = make_uint4(f2tf(na1.x), f2tf(na1.y), f2tf(na1.z), f2tf(na1.w));
            *(uint4*)&Bs[nb][lr     ][lq] = make_uint4(f2tf(nb0.x), f2tf(nb0.y), f2tf(nb0.z), f2tf(nb0.w));
            *(uint4*)&Bs[nb][lr + 64][lq] = make_uint4(f2tf(nb1.x), f2tf(nb1.y), f2tf(nb1.z), f2tf(nb1.w));
        }
        __syncthreads();
    }

    #pragma unroll
    for (int i = 0; i < 2; i++) {
        const int rg = bm + wm * 32 + i * 16 + gid;
        #pragma unroll
        for (int j = 0; j < 8; j++) {
            const int cg = bn + wn * 64 + j * 8 + tig * 2;
            if (cg < N) {
                const float2 bb = *(const float2*)&bias[cg];
                float2 c01 = make_float2(acc[i][j][0] + bb.x, acc[i][j][1] + bb.y);
                float2 c23 = make_float2(acc[i][j][2] + bb.x, acc[i][j][3] + bb.y);
                *(float2*)&C[(size_t)rg * ldc + cg]       = c01;
                *(float2*)&C[(size_t)(rg + 8) * ldc + cg] = c23;
            }
        }
    }
}

// h_final = [H0[T-1], H1[T-1]] -> d_out tail
__global__ void copy_final(const float* __restrict__ H0,
                           const float* __restrict__ H1,
                           float* __restrict__ dst)
{
    const int i = blockIdx.x * blockDim.x + threadIdx.x;
    if (i < BH)          dst[i] = H0[(size_t)(T_ - 1) * BH + i];
    else if (i < 2 * BH) dst[i] = H1[(size_t)(T_ - 1) * BH + (i - BH)];
}

extern "C" void kernel_launch(void* const* d_in, const int* in_sizes, int n_in,
                              void* d_out, int out_size)
{
    (void)in_sizes; (void)n_in; (void)out_size;
    const int*   inputs = (const int*)  d_in[0];
    const float* hidden = (const float*)d_in[1];
    const float* emb    = (const float*)d_in[2];
    const float* Wx0    = (const float*)d_in[3];
    const float* Wx1    = (const float*)d_in[4];
    const float* Wh0    = (const float*)d_in[5];
    const float* bh0    = (const float*)d_in[6];
    const float* Wh1    = (const float*)d_in[7];
    const float* bh1    = (const float*)d_in[8];
    const float* Wy     = (const float*)d_in[9];
    const float* by     = (const float*)d_in[10];
    float* out = (float*)d_out;                    // [T*B*V][L*B*H]

    float *X0, *H0, *X1, *H1;
    cudaGetSymbolAddress((void**)&X0, g_X0);
    cudaGetSymbolAddress((void**)&H0, g_H0);
    cudaGetSymbolAddress((void**)&X1, g_X1);
    cudaGetSymbolAddress((void**)&H1, g_H1);

    const int rnn_smem = 2 * 64 * 132 * 4;   // 67584 B (> 48K static limit)
    cudaFuncSetAttribute(rnn_layer, cudaFuncAttributeMaxDynamicSharedMemorySize, rnn_smem);

    // A: X0 = gather(emb) @ Wx0^T + bh0
    gemm_tf32<<<dim3(H_ / 128, MTOT / 128), 256>>>(emb, Wx0, bh0, X0, inputs, H_, E_, H_);

    // B: layer-0 recurrence (persistent, tensor-core steps)
    bar_init<<<1, 128>>>();
    rnn_layer<<<128, 256, rnn_smem>>>(X0, hidden, Wh0, H0);

    // C: X1 = H0 @ Wx1^T + bh1
    gemm_tf32<<<dim3(H_ / 128, MTOT / 128), 256>>>(H0, Wx1, bh1, X1, nullptr, H_, H_, H_);

    // D: layer-1 recurrence
    bar_init<<<1, 128>>>();
    rnn_layer<<<128, 256, rnn_smem>>>(X1, hidden + BH, Wh1, H1);

    // E: logits = H1 @ Wy^T + by
    gemm_tf32<<<dim3((V_ + 127) / 128, MTOT / 128), 256>>>(H1, Wy, by, out, nullptr, V_, H_, V_);

    // F: h_final tail
    copy_final<<<(2 * BH + 255) / 256, 256>>>(H0, H1, out + (size_t)MTOT * V_);
}

// round 6
// speedup vs baseline: 1.6747x; 1.0787x over previous
#include <cuda_runtime.h>
#include <math.h>

// Problem constants: T=70, B=64, V=10000, E=512, H=1024, L=2
#define T_  70
#define B_  64
#define V_  10000
#define E_  512
#define H_  1024
#define MTOT (T_ * B_)          // 4480 = 35 * 128
#define BH   (B_ * H_)          // 65536

// Scratch (__device__ globals: allocation-free rule)
__device__ float    g_X0[(size_t)MTOT * H_];
__device__ float    g_H0[(size_t)MTOT * H_];
__device__ float    g_X1[(size_t)MTOT * H_];
__device__ float    g_H1[(size_t)MTOT * H_];
__device__ float    g_P[(size_t)8 * BH];        // k-split partials [8][64][1024]
__device__ unsigned g_Htf[(size_t)T_ * BH];     // tf32 h_t, k-pair interleaved (rnn A)
__device__ unsigned g_flags[128];               // per-block barrier flags

// tf32 pre-converted GEMM operands
__device__ unsigned g_emb_tf[(size_t)V_ * E_];
__device__ unsigned g_Wx0tf[(size_t)H_ * E_];
__device__ unsigned g_Wx1tf[(size_t)H_ * H_];
__device__ unsigned g_Wytf [(size_t)V_ * H_];
__device__ unsigned g_H0lin[(size_t)MTOT * H_]; // tf32 linear h (gemm A-side)
__device__ unsigned g_H1lin[(size_t)MTOT * H_];

__global__ void bar_init() { g_flags[threadIdx.x] = 0u; }

__device__ __forceinline__ unsigned f2tf(float x) {
    unsigned r; asm("cvt.rna.tf32.f32 %0, %1;" : "=r"(r) : "f"(x)); return r;
}

// fp32 -> tf32(rna) bulk convert (n4 = n/4 float4s)
__global__ void cvt_tf32(const float* __restrict__ s, unsigned* __restrict__ d, int n4) {
    const int i = blockIdx.x * 256 + threadIdx.x;
    if (i < n4) {
        const float4 v = ((const float4*)s)[i];
        ((uint4*)d)[i] = make_uint4(f2tf(v.x), f2tf(v.y), f2tf(v.z), f2tf(v.w));
    }
}

// Contention-free grid barrier (128 co-resident blocks, 1/SM).
__device__ __forceinline__ void gridbar(int bid, unsigned phase) {
    __threadfence();
    __syncthreads();
    if (threadIdx.x == 0)
        atomicExch(&g_flags[bid], phase);
    if (threadIdx.x < 128) {
        volatile unsigned* vf = g_flags;
        while (vf[threadIdx.x] < phase) __nanosleep(32);
    }
    __syncthreads();
    __threadfence();
}

__device__ __forceinline__ void mma_tf32(float c[4], const unsigned a[4], const unsigned b[2]) {
    asm volatile(
        "mma.sync.aligned.m16n8k8.row.col.f32.tf32.tf32.f32 "
        "{%0,%1,%2,%3}, {%4,%5,%6,%7}, {%8,%9}, {%0,%1,%2,%3};\n"
        : "+f"(c[0]), "+f"(c[1]), "+f"(c[2]), "+f"(c[3])
        : "r"(a[0]), "r"(a[1]), "r"(a[2]), "r"(a[3]), "r"(b[0]), "r"(b[1]));
}

// ---------------------------------------------------------------------------
// Persistent recurrence (tensor cores). 128 blocks x 256 threads.
// Block (ntile=bid>>3, ks=bid&7) owns W rows [ntile*64,+64) x k [ks*128,+128)
// in SMEM as tf32 hi/lo split. Warps: wk=wid&1 (64-k half), wn=wid>>1 (16n).
// After MMA: wk=1 accs go through SMEM and are added by wk=0 -> ONE partial
// slice per block (8 total). Reduce sums 8 partials + X, tanh, writes
// h fp32 (Hall), tf32-interleaved (g_Htf, rnn A-side) and tf32-linear (Hlin,
// gemm A-side).
// ---------------------------------------------------------------------------
__global__ __launch_bounds__(256) void rnn_layer(
    const float* __restrict__ X, const float* __restrict__ hinit,
    const float* __restrict__ W, float* __restrict__ Hall,
    unsigned* __restrict__ Hlin)
{
    extern __shared__ unsigned sw[];
    unsigned* Whi = sw;                      // [64][132]
    unsigned* Wlo = sw + 64 * 132;           // [64][132]
    float*    Pb  = (float*)(sw + 2 * 64 * 132);  // [64][72] k-half merge buffer

    const int tid = threadIdx.x;
    const int bid = blockIdx.x;
    const int ntile = bid >> 3;
    const int ks    = bid & 7;
    const int n0    = ntile * 64;
    const int kb    = ks * 128;

    // Load + split W slice once
    {
        const int r  = tid >> 2;
        const int q4 = (tid & 3) * 4;
        #pragma unroll
        for (int s = 0; s < 8; s++) {
            const int c = q4 + s * 16;
            const float4 w = *(const float4*)&W[(size_t)(n0 + r) * H_ + kb + c];
            unsigned h0 = f2tf(w.x), h1 = f2tf(w.y), h2 = f2tf(w.z), h3 = f2tf(w.w);
            unsigned* ph = &Whi[r * 132 + c];
            unsigned* pl = &Wlo[r * 132 + c];
            ph[0] = h0; ph[1] = h1; ph[2] = h2; ph[3] = h3;
            pl[0] = f2tf(w.x - __uint_as_float(h0));
            pl[1] = f2tf(w.y - __uint_as_float(h1));
            pl[2] = f2tf(w.z - __uint_as_float(h2));
            pl[3] = f2tf(w.w - __uint_as_float(h3));
        }
    }
    __syncthreads();

    const int wid  = tid >> 5, lane = tid & 31;
    const int wk   = wid & 1;
    const int wn   = wid >> 1;
    const int gid  = lane >> 2, tig = lane & 3;
    const int kwb  = kb + wk * 64;
    const int klb  = wk * 64;

    float* Pp = g_P + (size_t)ks * BH;

    // Reduce mapping: thread covers elements e, e+1 of [64][1024]
    const int e  = bid * 512 + tid * 2;
    const int rm = e >> 10;
    const int rn = e & 1023;
    const int b8 = rn & ~7;
    const int o0 = rn & 7;                   // even
    const int tp0 = b8 + ((o0 & 3) * 2) + (o0 >> 2);
    const int tp1 = b8 + (((o0 + 1) & 3) * 2) + ((o0 + 1) >> 2);

    unsigned phase = 0;

    for (int t = 0; t < T_; t++) {
        float acc[4][2][4];
        #pragma unroll
        for (int im = 0; im < 4; im++)
            #pragma unroll
            for (int j = 0; j < 2; j++)
                #pragma unroll
                for (int q = 0; q < 4; q++) acc[im][j][q] = 0.f;

        const unsigned* Hp = g_Htf + (size_t)(t - 1) * BH;   // valid for t>0

        #pragma unroll 2
        for (int kk = 0; kk < 8; kk++) {
            const int kcol = kwb + kk * 8;
            unsigned af[4][4];
            if (t == 0) {
                #pragma unroll
                for (int im = 0; im < 4; im++) {
                    const int r0 = im * 16 + gid;
                    af[im][0] = f2tf(hinit[(size_t)r0 * H_ + kcol + tig]);
                    af[im][1] = f2tf(hinit[(size_t)(r0 + 8) * H_ + kcol + tig]);
                    af[im][2] = f2tf(hinit[(size_t)r0 * H_ + kcol + tig + 4]);
                    af[im][3] = f2tf(hinit[(size_t)(r0 + 8) * H_ + kcol + tig + 4]);
                }
            } else {
                #pragma unroll
                for (int im = 0; im < 4; im++) {
                    const int r0 = im * 16 + gid;
                    const uint2 p0 = *(const uint2*)&Hp[(size_t)r0 * H_ + kcol + tig * 2];
                    const uint2 p1 = *(const uint2*)&Hp[(size_t)(r0 + 8) * H_ + kcol + tig * 2];
                    af[im][0] = p0.x; af[im][1] = p1.x;
                    af[im][2] = p0.y; af[im][3] = p1.y;
                }
            }
            #pragma unroll
            for (int j = 0; j < 2; j++) {
                const int wrow = (wn * 16 + j * 8 + gid) * 132 + klb + kk * 8;
                unsigned bh[2] = { Whi[wrow + tig], Whi[wrow + tig + 4] };
                unsigned bl[2] = { Wlo[wrow + tig], Wlo[wrow + tig + 4] };
                #pragma unroll
                for (int im = 0; im < 4; im++) {
                    mma_tf32(acc[im][j], af[im], bh);
                    mma_tf32(acc[im][j], af[im], bl);
                }
            }
        }

        // Merge the two k-halves inside the block: wk=1 -> smem, wk=0 adds.
        if (wk == 1) {
            #pragma unroll
            for (int im = 0; im < 4; im++) {
                const int r0 = im * 16 + gid;
                #pragma unroll
                for (int j = 0; j < 2; j++) {
                    const int col = wn * 16 + j * 8 + tig * 2;
                    *(float2*)&Pb[r0 * 72 + col] =
                        make_float2(acc[im][j][0], acc[im][j][1]);
                    *(float2*)&Pb[(r0 + 8) * 72 + col] =
                        make_float2(acc[im][j][2], acc[im][j][3]);
                }
            }
        }
        __syncthreads();
        if (wk == 0) {
            #pragma unroll
            for (int im = 0; im < 4; im++) {
                const int r0 = im * 16 + gid;
                #pragma unroll
                for (int j = 0; j < 2; j++) {
                    const int col = wn * 16 + j * 8 + tig * 2;
                    const float2 a0 = *(const float2*)&Pb[r0 * 72 + col];
                    const float2 a1 = *(const float2*)&Pb[(r0 + 8) * 72 + col];
                    *(float2*)&Pp[(size_t)r0 * H_ + n0 + col] =
                        make_float2(acc[im][j][0] + a0.x, acc[im][j][1] + a0.y);
                    *(float2*)&Pp[(size_t)(r0 + 8) * H_ + n0 + col] =
                        make_float2(acc[im][j][2] + a1.x, acc[im][j][3] + a1.y);
                }
            }
        }

        gridbar(bid, ++phase);

        // Reduce 8 partials + X, tanh -> Hall fp32 + Htf (interleaved) + Hlin
        {
            const float2 xv = *(const float2*)&X[(size_t)t * BH + e];
            float s0 = xv.x, s1 = xv.y;
            const size_t base = (size_t)rm * H_ + rn;
            #pragma unroll
            for (int j = 0; j < 8; j++) {
                const float2 v = __ldcg((const float2*)&g_P[(size_t)j * BH + base]);
                s0 += v.x; s1 += v.y;
            }
            const float h0 = tanhf(s0), h1 = tanhf(s1);
            *(float2*)&Hall[(size_t)t * BH + e] = make_float2(h0, h1);
            const unsigned u0 = f2tf(h0), u1 = f2tf(h1);
            unsigned* Ht = g_Htf + (size_t)t * BH + (size_t)rm * H_;
            Ht[tp0] = u0;
            Ht[tp1] = u1;
            *(uint2*)&Hlin[(size_t)t * BH + e] = make_uint2(u0, u1);
        }

        gridbar(bid, ++phase);
    }
}

// ---------------------------------------------------------------------------
// TF32 GEMM v3: operands PRE-CONVERTED to tf32 in gmem -> pure uint datapath,
// cp.async 3-stage pipeline, no conversion in-kernel.
// C[m,n] = A[m,:] . B[n,:] + bias[n]; A [M,K] (optional gather), B [N,K].
// Block 128x128, kc=16, 8 warps (4m x 2n), warp 32m x 64n, stride-20 smem
// rows (scalar LDS conflict-free), B-fragments batched 4 j's ahead.
// ---------------------------------------------------------------------------
#define GS 2560          // words per stage per array (128*20)

__global__ __launch_bounds__(256, 2) void gemm_tf32(
    const unsigned* __restrict__ A, const unsigned* __restrict__ Bm,
    const float* __restrict__ bias, float* __restrict__ C,
    const int* __restrict__ gidx, int N, int K, int ldc)
{
    extern __shared__ unsigned sg[];      // As: 3*GS, Bs: 3*GS
    #define AS(st, r, c) sg[(st) * GS + (r) * 20 + (c)]
    #define BS(st, r, c) sg[3 * GS + (st) * GS + (r) * 20 + (c)]

    const int tid  = threadIdx.x;
    const int lane = tid & 31, warp = tid >> 5;
    const int wm = warp >> 1, wn = warp & 1;
    const int gid = lane >> 2, tig = lane & 3;
    const int bm = blockIdx.y * 128, bn = blockIdx.x * 128;

    // Fill mapping: thread covers rows lr, lr+64 at k-quad lq
    const int lr = tid >> 2;
    const int lq = (tid & 3) * 4;
    const int ar0 = gidx ? gidx[bm + lr]      : (bm + lr);
    const int ar1 = gidx ? gidx[bm + lr + 64] : (bm + lr + 64);
    const unsigned* Ar0 = A + (size_t)ar0 * K;
    const unsigned* Ar1 = A + (size_t)ar1 * K;
    const int nr0 = min(bn + lr, N - 1);            // clamp OOB rows
    const int nr1 = min(bn + lr + 64, N - 1);
    const unsigned* Br0 = Bm + (size_t)nr0 * K;
    const unsigned* Br1 = Bm + (size_t)nr1 * K;

    const unsigned smem_base = (unsigned)__cvta_generic_to_shared(sg);
    const unsigned dA0 = smem_base + (lr * 20 + lq) * 4;
    const unsigned dA1 = smem_base + ((lr + 64) * 20 + lq) * 4;
    const unsigned dB0 = smem_base + (3 * GS + lr * 20 + lq) * 4;
    const unsigned dB1 = smem_base + (3 * GS + (lr + 64) * 20 + lq) * 4;

    const int nst = K >> 4;

    #define ISSUE(st, s)                                                     \
        { const int ko = (s) * 16 + lq; const unsigned so = (st) * GS * 4;   \
          asm volatile("cp.async.cg.shared.global [%0], [%1], 16;\n"         \
                       :: "r"(dA0 + so), "l"(Ar0 + ko));                     \
          asm volatile("cp.async.cg.shared.global [%0], [%1], 16;\n"         \
                       :: "r"(dA1 + so), "l"(Ar1 + ko));                     \
          asm volatile("cp.async.cg.shared.global [%0], [%1], 16;\n"         \
                       :: "r"(dB0 + so), "l"(Br0 + ko));                     \
          asm volatile("cp.async.cg.shared.global [%0], [%1], 16;\n"         \
                       :: "r"(dB1 + so), "l"(Br1 + ko));                     \
          asm volatile("cp.async.commit_group;\n"); }

    ISSUE(0, 0)
    ISSUE(1, 1)

    float acc[2][8][4];
    #pragma unroll
    for (int i = 0; i < 2; i++)
        #pragma unroll
        for (int j = 0; j < 8; j++)
            #pragma unroll
            for (int q = 0; q < 4; q++) acc[i][j][q] = 0.f;

    for (int s = 0; s < nst; s++) {
        if (s == nst - 1) asm volatile("cp.async.wait_group 0;\n");
        else              asm volatile("cp.async.wait_group 1;\n");
        __syncthreads();

        if (s + 2 < nst) ISSUE((s + 2) % 3, s + 2)

        const int st = s % 3;
        #pragma unroll
        for (int kk = 0; kk < 16; kk += 8) {
            unsigned af[2][4];
            #pragma unroll
            for (int i = 0; i < 2; i++) {
                const int r = wm * 32 + i * 16 + gid;
                af[i][0] = AS(st, r,     kk + tig);
                af[i][1] = AS(st, r + 8, kk + tig);
                af[i][2] = AS(st, r,     kk + tig + 4);
                af[i][3] = AS(st, r + 8, kk + tig + 4);
            }
            #pragma unroll
            for (int jb = 0; jb < 2; jb++) {
                unsigned bf[4][2];
                #pragma unroll
                for (int j2 = 0; j2 < 4; j2++) {
                    const int r = wn * 64 + (jb * 4 + j2) * 8 + gid;
                    bf[j2][0] = BS(st, r, kk + tig);
                    bf[j2][1] = BS(st, r, kk + tig + 4);
                }
                #pragma unroll
                for (int j2 = 0; j2 < 4; j2++) {
                    mma_tf32(acc[0][jb * 4 + j2], af[0], bf[j2]);
                    mma_tf32(acc[1][jb * 4 + j2], af[1], bf[j2]);
                }
            }
        }
    }
    #undef ISSUE
    #undef AS
    #undef BS

    // Epilogue: c0/c1 -> (row, col..col+1), c2/c3 -> (row+8, ...)
    #pragma unroll
    for (int i = 0; i < 2; i++) {
        const int rg = bm + wm * 32 + i * 16 + gid;
        #pragma unroll
        for (int j = 0; j < 8; j++) {
            const int cg = bn + wn * 64 + j * 8 + tig * 2;
            if (cg < N) {
                const float2 bb = *(const float2*)&bias[cg];
                float2 c01 = make_float2(acc[i][j][0] + bb.x, acc[i][j][1] + bb.y);
                float2 c23 = make_float2(acc[i][j][2] + bb.x, acc[i][j][3] + bb.y);
                *(float2*)&C[(size_t)rg * ldc + cg]       = c01;
                *(float2*)&C[(size_t)(rg + 8) * ldc + cg] = c23;
            }
        }
    }
}

// h_final = [H0[T-1], H1[T-1]] -> d_out tail
__global__ void copy_final(const float* __restrict__ H0,
                           const float* __restrict__ H1,
                           float* __restrict__ dst)
{
    const int i = blockIdx.x * blockDim.x + threadIdx.x;
    if (i < BH)          dst[i] = H0[(size_t)(T_ - 1) * BH + i];
    else if (i < 2 * BH) dst[i] = H1[(size_t)(T_ - 1) * BH + (i - BH)];
}

extern "C" void kernel_launch(void* const* d_in, const int* in_sizes, int n_in,
                              void* d_out, int out_size)
{
    (void)in_sizes; (void)n_in; (void)out_size;
    const int*   inputs = (const int*)  d_in[0];
    const float* hidden = (const float*)d_in[1];
    const float* emb    = (const float*)d_in[2];
    const float* Wx0    = (const float*)d_in[3];
    const float* Wx1    = (const float*)d_in[4];
    const float* Wh0    = (const float*)d_in[5];
    const float* bh0    = (const float*)d_in[6];
    const float* Wh1    = (const float*)d_in[7];
    const float* bh1    = (const float*)d_in[8];
    const float* Wy     = (const float*)d_in[9];
    const float* by     = (const float*)d_in[10];
    float* out = (float*)d_out;                    // [T*B*V][L*B*H]

    float *X0, *H0, *X1, *H1;
    unsigned *embT, *Wx0T, *Wx1T, *WyT, *H0lin, *H1lin;
    cudaGetSymbolAddress((void**)&X0, g_X0);
    cudaGetSymbolAddress((void**)&H0, g_H0);
    cudaGetSymbolAddress((void**)&X1, g_X1);
    cudaGetSymbolAddress((void**)&H1, g_H1);
    cudaGetSymbolAddress((void**)&embT, g_emb_tf);
    cudaGetSymbolAddress((void**)&Wx0T, g_Wx0tf);
    cudaGetSymbolAddress((void**)&Wx1T, g_Wx1tf);
    cudaGetSymbolAddress((void**)&WyT,  g_Wytf);
    cudaGetSymbolAddress((void**)&H0lin, g_H0lin);
    cudaGetSymbolAddress((void**)&H1lin, g_H1lin);

    const int rnn_smem  = 2 * 64 * 132 * 4 + 64 * 72 * 4;   // 86016 B
    const int gemm_smem = 6 * GS * 4;                        // 61440 B
    cudaFuncSetAttribute(rnn_layer, cudaFuncAttributeMaxDynamicSharedMemorySize, rnn_smem);
    cudaFuncSetAttribute(gemm_tf32, cudaFuncAttributeMaxDynamicSharedMemorySize, gemm_smem);

    // Pre-convert GEMM operands to tf32 (pure bandwidth, ~25us total)
    {
        const int n_emb = V_ * E_ / 4, n_w0 = H_ * E_ / 4,
                  n_w1 = H_ * H_ / 4, n_wy = V_ * H_ / 4;
        cvt_tf32<<<(n_emb + 255) / 256, 256>>>(emb, embT, n_emb);
        cvt_tf32<<<(n_w0 + 255) / 256, 256>>>(Wx0, Wx0T, n_w0);
        cvt_tf32<<<(n_w1 + 255) / 256, 256>>>(Wx1, Wx1T, n_w1);
        cvt_tf32<<<(n_wy + 255) / 256, 256>>>(Wy, WyT, n_wy);
    }

    // A: X0 = gather(emb_tf) @ Wx0^T + bh0
    gemm_tf32<<<dim3(H_ / 128, MTOT / 128), 256, gemm_smem>>>(
        embT, Wx0T, bh0, X0, inputs, H_, E_, H_);

    // B: layer-0 recurrence
    bar_init<<<1, 128>>>();
    rnn_layer<<<128, 256, rnn_smem>>>(X0, hidden, Wh0, H0, H0lin);

    // C: X1 = H0 @ Wx1^T + bh1
    gemm_tf32<<<dim3(H_ / 128, MTOT / 128), 256, gemm_smem>>>(
        H0lin, Wx1T, bh1, X1, nullptr, H_, H_, H_);

    // D: layer-1 recurrence
    bar_init<<<1, 128>>>();
    rnn_layer<<<128, 256, rnn_smem>>>(X1, hidden + BH, Wh1, H1, H1lin);

    // E: logits = H1 @ Wy^T + by
    gemm_tf32<<<dim3((V_ + 127) / 128, MTOT / 128), 256, gemm_smem>>>(
        H1lin, WyT, by, out, nullptr, V_, H_, V_);

    // F: h_final tail
    copy_final<<<(2 * BH + 255) / 256, 256>>>(H0, H1, out + (size_t)MTOT * V_);
}